// round 1
// baseline (speedup 1.0000x reference)
#include <cuda_runtime.h>

// Problem constants
#define Bb 8
#define Nn 512
#define Tt 64
#define Dd 128
#define Hh 8
#define DKk 16
#define Kk 3

#define TILE (Tt * Dd)          // 8192 floats per (b,n) tensor tile
#define QS (Dd + 4)             // padded row stride for q/k/v tiles (132)
#define WCH 16                  // din chunk size for weight staging
#define SW_FLOATS (Kk * WCH * Dd)   // 6144 floats weight-stage buffer
#define SMEM_FLOATS (3 * TILE + 3 * Tt * QS + SW_FLOATS)  // 56064
#define SMEM_BYTES (SMEM_FLOATS * 4)                      // 224256

// Pre-transposed weights (prep kernel fills these each launch)
__device__ float g_Wq_t[Kk * Dd * Dd];   // [(j*D + din)*D + dout]
__device__ float g_Wk_t[Kk * Dd * Dd];
__device__ float g_Wv_t[Dd * Dd];        // [din*D + e]
__device__ float g_Wo_t[Dd * Dd];

__global__ void prep_kernel(const float* __restrict__ Wq, const float* __restrict__ Wk,
                            const float* __restrict__ Wv, const float* __restrict__ Wo) {
    int i = blockIdx.x * blockDim.x + threadIdx.x;
    const int nConv = Kk * Dd * Dd;  // 49152
    if (i < nConv) {
        // i = (j*D + din)*D + dout
        int dout = i & (Dd - 1);
        int rem = i >> 7;           // j*D + din
        int din = rem & (Dd - 1);
        int j = rem >> 7;
        g_Wq_t[i] = Wq[(dout * Dd + din) * Kk + j];
        g_Wk_t[i] = Wk[(dout * Dd + din) * Kk + j];
    } else {
        int i2 = i - nConv;
        if (i2 < Dd * Dd) {
            int e = i2 & (Dd - 1);
            int d = i2 >> 7;
            g_Wv_t[i2] = Wv[e * Dd + d];
            g_Wo_t[i2] = Wo[e * Dd + d];
        }
    }
}

// Causal/same temporal conv as GEMM over (din, j). Each thread: 4 t x 4 dout outputs.
// out[t][dout] = bias[dout] + sum_{j,din} Wt[(j*D+din)*D+dout] * in[t - L + j][din]
template <int L>
__device__ __forceinline__ void conv_block(
    const float* __restrict__ s_in,     // [T][D]
    const float* __restrict__ Wt,       // global, [(j*D+din)*D + dout]
    const float* __restrict__ bias,
    float* __restrict__ s_out,          // [T][QS]
    float* s_w, int tid, int t0, int d0)
{
    float acc[4][4];
#pragma unroll
    for (int a = 0; a < 4; a++)
#pragma unroll
        for (int c = 0; c < 4; c++) acc[a][c] = 0.f;

#pragma unroll 1
    for (int c0 = 0; c0 < Dd; c0 += WCH) {
        // stage W chunk: s_w[(j*WCH + i)*D + dout] = Wt[(j*D + c0+i)*D + dout]
#pragma unroll
        for (int r = 0; r < (SW_FLOATS / 4) / 512; r++) {  // 3 iters
            int fl = (tid + r * 512) * 4;
            int dout = fl & (Dd - 1);
            int row = fl >> 7;              // j*WCH + i
            int i = row & (WCH - 1);
            int j = row / WCH;
            *(float4*)(s_w + fl) = *(const float4*)(Wt + (j * Dd + c0 + i) * Dd + dout);
        }
        __syncthreads();
#pragma unroll
        for (int i = 0; i < WCH; i++) {
            int din = c0 + i;
            float x[6];
#pragma unroll
            for (int a = 0; a < 6; a++) {
                int tt = t0 - L + a;
                x[a] = ((unsigned)tt < (unsigned)Tt) ? s_in[tt * Dd + din] : 0.f;
            }
#pragma unroll
            for (int j = 0; j < Kk; j++) {
                float4 w = *(const float4*)(s_w + (j * WCH + i) * Dd + d0);
#pragma unroll
                for (int a = 0; a < 4; a++) {
                    acc[a][0] = fmaf(w.x, x[a + j], acc[a][0]);
                    acc[a][1] = fmaf(w.y, x[a + j], acc[a][1]);
                    acc[a][2] = fmaf(w.z, x[a + j], acc[a][2]);
                    acc[a][3] = fmaf(w.w, x[a + j], acc[a][3]);
                }
            }
        }
        __syncthreads();
    }
    float4 bb = *(const float4*)(bias + d0);
#pragma unroll
    for (int a = 0; a < 4; a++) {
        float4 o = make_float4(acc[a][0] + bb.x, acc[a][1] + bb.y,
                               acc[a][2] + bb.z, acc[a][3] + bb.w);
        *(float4*)(s_out + (t0 + a) * QS + d0) = o;
    }
}

// Dense [T,128] @ [128,128] GEMM; writes either smem (stride QS) or gmem (stride D)
__device__ __forceinline__ void gemm_block(
    const float* __restrict__ s_in, int in_stride,
    const float* __restrict__ Wt,   // [din*D + e]
    const float* __restrict__ bias,
    float* s_w, int tid, int t0, int d0,
    float* __restrict__ outp, int out_stride)
{
    float acc[4][4];
#pragma unroll
    for (int a = 0; a < 4; a++)
#pragma unroll
        for (int c = 0; c < 4; c++) acc[a][c] = 0.f;

#pragma unroll 1
    for (int c0 = 0; c0 < Dd; c0 += WCH) {
        {   // stage WCH*128 = 2048 floats, one float4 per thread
            int fl = tid * 4;
            int dout = fl & (Dd - 1);
            int i = fl >> 7;
            *(float4*)(s_w + fl) = *(const float4*)(Wt + (c0 + i) * Dd + dout);
        }
        __syncthreads();
#pragma unroll
        for (int i = 0; i < WCH; i++) {
            int din = c0 + i;
            float4 w = *(const float4*)(s_w + i * Dd + d0);
#pragma unroll
            for (int a = 0; a < 4; a++) {
                float x = s_in[(t0 + a) * in_stride + din];
                acc[a][0] = fmaf(w.x, x, acc[a][0]);
                acc[a][1] = fmaf(w.y, x, acc[a][1]);
                acc[a][2] = fmaf(w.z, x, acc[a][2]);
                acc[a][3] = fmaf(w.w, x, acc[a][3]);
            }
        }
        __syncthreads();
    }
    float4 bb = *(const float4*)(bias + d0);
#pragma unroll
    for (int a = 0; a < 4; a++) {
        float4 o = make_float4(acc[a][0] + bb.x, acc[a][1] + bb.y,
                               acc[a][2] + bb.z, acc[a][3] + bb.w);
        *(float4*)(outp + (t0 + a) * out_stride + d0) = o;
    }
}

__global__ void __launch_bounds__(512)
attn_kernel(const float* __restrict__ query, const float* __restrict__ key,
            const float* __restrict__ value, const int* __restrict__ mask,
            const float* __restrict__ bq, const float* __restrict__ bk,
            const float* __restrict__ bv, const float* __restrict__ bo,
            float* __restrict__ out)
{
    extern __shared__ float sm[];
    float* s_inq = sm;                       // [T][D]   (later reused as x)
    float* s_ink = s_inq + TILE;             // [T][D]
    float* s_inv = s_ink + TILE;             // [T][D]
    float* s_q   = s_inv + TILE;             // [T][QS]
    float* s_k   = s_q + Tt * QS;            // [T][QS]
    float* s_v   = s_k + Tt * QS;            // [T][QS]
    float* s_w   = s_v + Tt * QS;            // 6144 floats staging / mask

    const int tid = threadIdx.x;
    const int bn = blockIdx.x;
    const int b = bn >> 9;                   // N = 512
    const long long base = (long long)bn * TILE;

    const int d0 = (tid & 31) * 4;
    const int t0 = (tid >> 5) * 4;

    // Phase 0: load input tiles
    {
        const float4* gq = (const float4*)(query + base);
        const float4* gk = (const float4*)(key + base);
        const float4* gv = (const float4*)(value + base);
        float4* s1 = (float4*)s_inq;
        float4* s2 = (float4*)s_ink;
        float4* s3 = (float4*)s_inv;
#pragma unroll
        for (int r = 0; r < 4; r++) {
            int idx = tid + r * 512;   // 2048 float4 per tile
            s1[idx] = gq[idx];
            s2[idx] = gk[idx];
            s3[idx] = gv[idx];
        }
    }
    __syncthreads();

    // Phase 1: q = causal conv (L=2), k = same conv (L=1), v = GEMM
    conv_block<2>(s_inq, g_Wq_t, bq, s_q, s_w, tid, t0, d0);
    conv_block<1>(s_ink, g_Wk_t, bk, s_k, s_w, tid, t0, d0);
    gemm_block(s_inv, Dd, g_Wv_t, bv, s_w, tid, t0, d0, s_v, QS);

    // Phase 2: stage mask rows (padded stride 66 to dodge bank conflicts)
    {
        int* s_mask = (int*)s_w;
        const int* gm = mask + b * (Tt * Tt);
#pragma unroll
        for (int r = 0; r < 8; r++) {
            int m = tid + r * 512;      // 4096 ints
            int mt = m >> 6, ms = m & 63;
            s_mask[mt * 66 + ms] = gm[m];
        }
    }
    __syncthreads();

    // Phase 3: attention. thread <-> (head h, row t); p[64] kept in registers.
    {
        const int h = tid >> 6;
        const int t = tid & 63;
        const float* qrow = s_q + t * QS + h * DKk;
        const float* kb = s_k + h * DKk;
        const float* vb = s_v + h * DKk;
        const int* mrow = (const int*)s_w + t * 66;

        float qv[16];
#pragma unroll
        for (int u = 0; u < 4; u++) {
            float4 f = *(const float4*)(qrow + 4 * u);
            qv[4 * u + 0] = f.x; qv[4 * u + 1] = f.y;
            qv[4 * u + 2] = f.z; qv[4 * u + 3] = f.w;
        }

        float p[64];
        float mx = -3.0e38f;
#pragma unroll
        for (int s = 0; s < 64; s++) {
            const float* kr = kb + s * QS;
            float a0 = 0.f, a1 = 0.f, a2 = 0.f, a3 = 0.f;
#pragma unroll
            for (int u = 0; u < 4; u++) {
                float4 f = *(const float4*)(kr + 4 * u);
                a0 = fmaf(qv[4 * u + 0], f.x, a0);
                a1 = fmaf(qv[4 * u + 1], f.y, a1);
                a2 = fmaf(qv[4 * u + 2], f.z, a2);
                a3 = fmaf(qv[4 * u + 3], f.w, a3);
            }
            float sc = ((a0 + a1) + (a2 + a3)) * 0.25f;   // 1/sqrt(16)
            sc = (mrow[s] == 0) ? -1.0e9f : sc;
            p[s] = sc;
            mx = fmaxf(mx, sc);
        }

        float sum = 0.f;
#pragma unroll
        for (int s = 0; s < 64; s++) {
            float e = __expf(p[s] - mx);
            p[s] = e;
            sum += e;
        }
        float inv = 1.0f / sum;

        float xa[16];
#pragma unroll
        for (int u = 0; u < 16; u++) xa[u] = 0.f;
#pragma unroll
        for (int s = 0; s < 64; s++) {
            float ps = p[s];
            const float* vr = vb + s * QS;
#pragma unroll
            for (int u = 0; u < 4; u++) {
                float4 f = *(const float4*)(vr + 4 * u);
                xa[4 * u + 0] = fmaf(ps, f.x, xa[4 * u + 0]);
                xa[4 * u + 1] = fmaf(ps, f.y, xa[4 * u + 1]);
                xa[4 * u + 2] = fmaf(ps, f.z, xa[4 * u + 2]);
                xa[4 * u + 3] = fmaf(ps, f.w, xa[4 * u + 3]);
            }
        }

        // write x row into s_inq (reused as x buffer, [T][D])
        float* xrow = s_inq + t * Dd + h * DKk;
#pragma unroll
        for (int u = 0; u < 4; u++) {
            float4 o = make_float4(xa[4 * u + 0] * inv, xa[4 * u + 1] * inv,
                                   xa[4 * u + 2] * inv, xa[4 * u + 3] * inv);
            *(float4*)(xrow + 4 * u) = o;
        }
    }
    __syncthreads();

    // Phase 4: output projection, write straight to gmem
    gemm_block(s_inq, Dd, g_Wo_t, bo, s_w, tid, t0, d0, out + base, Dd);
}

extern "C" void kernel_launch(void* const* d_in, const int* in_sizes, int n_in,
                              void* d_out, int out_size) {
    (void)in_sizes; (void)n_in; (void)out_size;
    const float* query = (const float*)d_in[0];
    const float* key   = (const float*)d_in[1];
    const float* value = (const float*)d_in[2];
    const int*   mask  = (const int*)d_in[3];
    const float* Wq = (const float*)d_in[4];
    const float* bq = (const float*)d_in[5];
    const float* Wk = (const float*)d_in[6];
    const float* bk = (const float*)d_in[7];
    const float* Wv = (const float*)d_in[8];
    const float* bv = (const float*)d_in[9];
    const float* Wo = (const float*)d_in[10];
    const float* bo = (const float*)d_in[11];
    float* out = (float*)d_out;

    cudaFuncSetAttribute(attn_kernel, cudaFuncAttributeMaxDynamicSharedMemorySize, SMEM_BYTES);

    // 49152 conv weights + 16384 dense weights = 65536 work items
    prep_kernel<<<256, 256>>>(Wq, Wk, Wv, Wo);
    attn_kernel<<<Bb * Nn, 512, SMEM_BYTES>>>(query, key, value, mask,
                                              bq, bk, bv, bo, out);
}

// round 2
// speedup vs baseline: 1.1984x; 1.1984x over previous
#include <cuda_runtime.h>

// Problem constants
#define Bb 8
#define Nn 512
#define Tt 64
#define Dd 128
#define Hh 8
#define DKk 16
#define Kk 3

#define XS 132                      // padded row stride (floats) for all tiles
#define TILEP (Tt * XS)             // 8448 floats per padded tile
#define WCH 16                      // din chunk
#define STAGE_F (2 * Kk * WCH * Dd + WCH * Dd)  // wq 6144 + wk 6144 + wv 2048 = 14336
#define MASK_I (Tt * 65)            // 4160 ints
#define SMEM_FLOATS (3 * TILEP + STAGE_F + MASK_I)   // 43840
#define SMEM_BYTES (SMEM_FLOATS * 4)                 // 175360

typedef unsigned long long ull;

__device__ __forceinline__ ull pk2(float lo, float hi) {
    ull r; asm("mov.b64 %0, {%1,%2};" : "=l"(r) : "f"(lo), "f"(hi)); return r;
}
__device__ __forceinline__ float2 upk2(ull a) {
    float2 f; asm("mov.b64 {%0,%1}, %2;" : "=f"(f.x), "=f"(f.y) : "l"(a)); return f;
}
__device__ __forceinline__ ull fma2(ull a, ull b, ull c) {
    ull d; asm("fma.rn.f32x2 %0, %1, %2, %3;" : "=l"(d) : "l"(a), "l"(b), "l"(c)); return d;
}
__device__ __forceinline__ ull add2(ull a, ull b) {
    ull d; asm("add.rn.f32x2 %0, %1, %2;" : "=l"(d) : "l"(a), "l"(b)); return d;
}

// Pre-transposed weights
__device__ float g_Wq_t[Kk * Dd * Dd];   // [(j*D + din)*D + dout]
__device__ float g_Wk_t[Kk * Dd * Dd];
__device__ float g_Wv_t[Dd * Dd];        // [din*D + e]
__device__ float g_Wo_t[Dd * Dd];

__global__ void prep_kernel(const float* __restrict__ Wq, const float* __restrict__ Wk,
                            const float* __restrict__ Wv, const float* __restrict__ Wo) {
    int i = blockIdx.x * blockDim.x + threadIdx.x;
    const int nConv = Kk * Dd * Dd;  // 49152
    if (i < nConv) {
        int dout = i & (Dd - 1);
        int rem = i >> 7;           // j*D + din
        int din = rem & (Dd - 1);
        int j = rem >> 7;
        g_Wq_t[i] = Wq[(dout * Dd + din) * Kk + j];
        g_Wk_t[i] = Wk[(dout * Dd + din) * Kk + j];
    } else {
        int i2 = i - nConv;
        if (i2 < Dd * Dd) {
            int e = i2 & (Dd - 1);
            int d = i2 >> 7;
            g_Wv_t[i2] = Wv[e * Dd + d];
            g_Wo_t[i2] = Wo[e * Dd + d];
        }
    }
}

// Stage one din-chunk of Wq|Wk|Wv into smem: 14336 floats, 7 float4/thread.
__device__ __forceinline__ void stage_phase1(float* s_stage, int tid, int c0) {
#pragma unroll
    for (int r = 0; r < 7; r++) {
        int f = tid * 4 + r * 2048;
        const float* src;
        if (f < 6144) {
            int j = f >> 11, rem = f & 2047, i = rem >> 7, dout = rem & 127;
            src = g_Wq_t + (j * Dd + c0 + i) * Dd + dout;
        } else if (f < 12288) {
            int f1 = f - 6144;
            int j = f1 >> 11, rem = f1 & 2047, i = rem >> 7, dout = rem & 127;
            src = g_Wk_t + (j * Dd + c0 + i) * Dd + dout;
        } else {
            int f2 = f - 12288;
            int i = f2 >> 7, dout = f2 & 127;
            src = g_Wv_t + (c0 + i) * Dd + dout;
        }
        *(float4*)(s_stage + f) = *(const float4*)src;
    }
}

// Conv chunk step: 8t x 8d per thread (douts d0..d0+3 and d0+64..d0+67), packed FMA.
// acc[t*4 + {0,1,2,3}] = pairs (d0,d0+1)(d0+2,d0+3)(d0+64,d0+65)(d0+66,d0+67)
template <int L>
__device__ __forceinline__ void conv_step(ull (&acc)[32], const float* __restrict__ s_in,
                                          const float* __restrict__ s_w,
                                          int t0, int d0, int c0) {
#pragma unroll
    for (int i = 0; i < WCH; i++) {
        int din = c0 + i;
        float x[10];
#pragma unroll
        for (int a = 0; a < 10; a++) {
            int tt = t0 - L + a;
            x[a] = ((unsigned)tt < (unsigned)Tt) ? s_in[tt * XS + din] : 0.f;
        }
#pragma unroll
        for (int j = 0; j < Kk; j++) {
            const float* wb = s_w + (j * WCH + i) * Dd;
            ulonglong2 w0 = *(const ulonglong2*)(wb + d0);
            ulonglong2 w1 = *(const ulonglong2*)(wb + d0 + 64);
#pragma unroll
            for (int t = 0; t < 8; t++) {
                ull xx = pk2(x[t + j], x[t + j]);
                acc[t * 4 + 0] = fma2(w0.x, xx, acc[t * 4 + 0]);
                acc[t * 4 + 1] = fma2(w0.y, xx, acc[t * 4 + 1]);
                acc[t * 4 + 2] = fma2(w1.x, xx, acc[t * 4 + 2]);
                acc[t * 4 + 3] = fma2(w1.y, xx, acc[t * 4 + 3]);
            }
        }
    }
}

__device__ __forceinline__ void conv_write(ull (&acc)[32], const float* __restrict__ bias,
                                           float* __restrict__ s_out, int t0, int d0) {
    ull b0 = pk2(bias[d0], bias[d0 + 1]);
    ull b1 = pk2(bias[d0 + 2], bias[d0 + 3]);
    ull b2 = pk2(bias[d0 + 64], bias[d0 + 65]);
    ull b3 = pk2(bias[d0 + 66], bias[d0 + 67]);
#pragma unroll
    for (int t = 0; t < 8; t++) {
        ulonglong2 oA, oB;
        oA.x = add2(acc[t * 4 + 0], b0);
        oA.y = add2(acc[t * 4 + 1], b1);
        oB.x = add2(acc[t * 4 + 2], b2);
        oB.y = add2(acc[t * 4 + 3], b3);
        *(ulonglong2*)(s_out + (t0 + t) * XS + d0) = oA;
        *(ulonglong2*)(s_out + (t0 + t) * XS + d0 + 64) = oB;
    }
}

// Dense GEMM chunk step: 8t x 4d per thread. acc[t*2 + {0,1}].
__device__ __forceinline__ void gemm_step(ull (&acc)[32], const float* __restrict__ s_in,
                                          const float* __restrict__ s_w,
                                          int t0, int d0, int c0) {
#pragma unroll
    for (int i = 0; i < WCH; i++) {
        int din = c0 + i;
        float x[8];
#pragma unroll
        for (int a = 0; a < 8; a++) x[a] = s_in[(t0 + a) * XS + din];
        ulonglong2 w = *(const ulonglong2*)(s_w + i * Dd + d0);
#pragma unroll
        for (int t = 0; t < 8; t++) {
            ull xx = pk2(x[t], x[t]);
            acc[t * 2 + 0] = fma2(w.x, xx, acc[t * 2 + 0]);
            acc[t * 2 + 1] = fma2(w.y, xx, acc[t * 2 + 1]);
        }
    }
}

__device__ __forceinline__ void gemm_write(ull (&acc)[32], const float* __restrict__ bias,
                                           float* __restrict__ outp, int out_stride,
                                           int t0, int d0) {
    ull b0 = pk2(bias[d0], bias[d0 + 1]);
    ull b1 = pk2(bias[d0 + 2], bias[d0 + 3]);
#pragma unroll
    for (int t = 0; t < 8; t++) {
        ulonglong2 o;
        o.x = add2(acc[t * 2 + 0], b0);
        o.y = add2(acc[t * 2 + 1], b1);
        *(ulonglong2*)(outp + (t0 + t) * out_stride + d0) = o;
    }
}

__global__ void __launch_bounds__(512)
attn_kernel(const float* __restrict__ query, const float* __restrict__ key,
            const float* __restrict__ value, const int* __restrict__ mask,
            const float* __restrict__ bq, const float* __restrict__ bk,
            const float* __restrict__ bv, const float* __restrict__ bo,
            float* __restrict__ out)
{
    extern __shared__ float sm[];
    float* s_x1 = sm;                        // q input -> q
    float* s_x2 = s_x1 + TILEP;              // k input -> k -> Wo stage
    float* s_x3 = s_x2 + TILEP;              // v input -> v
    float* s_stage = s_x3 + TILEP;           // weight staging -> x buffer
    int*   s_mask = (int*)(s_stage + STAGE_F);

    const int tid = threadIdx.x;
    const int bn = blockIdx.x;
    const int b = bn >> 9;                   // N = 512
    const long long base = (long long)bn * (Tt * Dd);

    // Phase 0: load input tiles (stride 132) + mask
    {
        const float4* gq = (const float4*)(query + base);
        const float4* gk = (const float4*)(key + base);
        const float4* gv = (const float4*)(value + base);
#pragma unroll
        for (int r = 0; r < 4; r++) {
            int idx = tid + r * 512;         // 2048 float4 per tile
            int e = idx * 4;
            int t = e >> 7, d = e & 127;
            int dst = t * XS + d;
            *(float4*)(s_x1 + dst) = gq[idx];
            *(float4*)(s_x2 + dst) = gk[idx];
            *(float4*)(s_x3 + dst) = gv[idx];
        }
        const int* gm = mask + b * (Tt * Tt);
#pragma unroll
        for (int r = 0; r < 8; r++) {
            int m = tid + r * 512;
            s_mask[(m >> 6) * 65 + (m & 63)] = gm[m];
        }
    }
    __syncthreads();

    // Phase 1: conv q (warps 0-3) || conv k (warps 4-7) || v gemm (warps 8-15)
    ull acc[32];
#pragma unroll
    for (int u = 0; u < 32; u++) acc[u] = 0ull;

    const int tg = tid & 127;
    const int cd0 = (tg & 15) * 4;           // conv d0
    const int ct0 = (tg >> 4) * 8;           // conv t0
    const int vg = tid & 255;
    const int gd0 = (vg & 31) * 4;           // gemm d0
    const int gt0 = (vg >> 5) * 8;           // gemm t0

#pragma unroll 1
    for (int c0 = 0; c0 < Dd; c0 += WCH) {
        stage_phase1(s_stage, tid, c0);
        __syncthreads();
        if (tid < 128)
            conv_step<2>(acc, s_x1, s_stage, ct0, cd0, c0);
        else if (tid < 256)
            conv_step<1>(acc, s_x2, s_stage + 6144, ct0, cd0, c0);
        else
            gemm_step(acc, s_x3, s_stage + 12288, gt0, gd0, c0);
        __syncthreads();
    }
    // write q/k/v over their input tiles
    if (tid < 128)       conv_write(acc, bq, s_x1, ct0, cd0);
    else if (tid < 256)  conv_write(acc, bk, s_x2, ct0, cd0);
    else                 gemm_write(acc, bv, s_x3, XS, gt0, gd0);
    __syncthreads();

    // Phase 2: attention. thread <-> (head h, row t)
    {
        const int h = tid >> 6;
        const int t = tid & 63;
        const float* qrow = s_x1 + t * XS + h * DKk;
        const float* kb = s_x2 + h * DKk;
        const float* vb = s_x3 + h * DKk;
        const int* mrow = s_mask + t * 65;

        ull qv[8];
        {
            ulonglong2 a0 = *(const ulonglong2*)(qrow + 0);
            ulonglong2 a1 = *(const ulonglong2*)(qrow + 4);
            ulonglong2 a2 = *(const ulonglong2*)(qrow + 8);
            ulonglong2 a3 = *(const ulonglong2*)(qrow + 12);
            qv[0] = a0.x; qv[1] = a0.y; qv[2] = a1.x; qv[3] = a1.y;
            qv[4] = a2.x; qv[5] = a2.y; qv[6] = a3.x; qv[7] = a3.y;
        }

        float p[64];
        float mx = -3.0e38f;
#pragma unroll
        for (int s = 0; s < 64; s++) {
            const float* kr = kb + s * XS;
            ulonglong2 k0 = *(const ulonglong2*)(kr + 0);
            ulonglong2 k1 = *(const ulonglong2*)(kr + 4);
            ulonglong2 k2 = *(const ulonglong2*)(kr + 8);
            ulonglong2 k3 = *(const ulonglong2*)(kr + 12);
            ull a0 = 0, a1 = 0, a2 = 0, a3 = 0;
            a0 = fma2(qv[0], k0.x, a0);
            a1 = fma2(qv[1], k0.y, a1);
            a2 = fma2(qv[2], k1.x, a2);
            a3 = fma2(qv[3], k1.y, a3);
            a0 = fma2(qv[4], k2.x, a0);
            a1 = fma2(qv[5], k2.y, a1);
            a2 = fma2(qv[6], k3.x, a2);
            a3 = fma2(qv[7], k3.y, a3);
            float2 r0 = upk2(add2(a0, a2));
            float2 r1 = upk2(add2(a1, a3));
            float sc = ((r0.x + r0.y) + (r1.x + r1.y)) * 0.25f;   // 1/sqrt(16)
            sc = (mrow[s] == 0) ? -1.0e9f : sc;
            p[s] = sc;
            mx = fmaxf(mx, sc);
        }

        float sum = 0.f;
#pragma unroll
        for (int s = 0; s < 64; s++) {
            float e = __expf(p[s] - mx);
            p[s] = e;
            sum += e;
        }
        float inv = 1.0f / sum;

        ull xa[8];
#pragma unroll
        for (int u = 0; u < 8; u++) xa[u] = 0ull;
#pragma unroll
        for (int s = 0; s < 64; s++) {
            ull pp = pk2(p[s], p[s]);
            const float* vr = vb + s * XS;
            ulonglong2 v0 = *(const ulonglong2*)(vr + 0);
            ulonglong2 v1 = *(const ulonglong2*)(vr + 4);
            ulonglong2 v2 = *(const ulonglong2*)(vr + 8);
            ulonglong2 v3 = *(const ulonglong2*)(vr + 12);
            xa[0] = fma2(pp, v0.x, xa[0]);
            xa[1] = fma2(pp, v0.y, xa[1]);
            xa[2] = fma2(pp, v1.x, xa[2]);
            xa[3] = fma2(pp, v1.y, xa[3]);
            xa[4] = fma2(pp, v2.x, xa[4]);
            xa[5] = fma2(pp, v2.y, xa[5]);
            xa[6] = fma2(pp, v3.x, xa[6]);
            xa[7] = fma2(pp, v3.y, xa[7]);
        }

        // x row -> s_stage (stride 132)
        float* xrow = s_stage + t * XS + h * DKk;
#pragma unroll
        for (int u = 0; u < 4; u++) {
            float2 lo = upk2(xa[2 * u]);
            float2 hi = upk2(xa[2 * u + 1]);
            *(float4*)(xrow + 4 * u) =
                make_float4(lo.x * inv, lo.y * inv, hi.x * inv, hi.y * inv);
        }
    }
    __syncthreads();

    // Phase 3: output projection (warps 8-15), Wo staged into s_x2
#pragma unroll
    for (int u = 0; u < 32; u++) acc[u] = 0ull;
#pragma unroll 1
    for (int c0 = 0; c0 < Dd; c0 += WCH) {
        {
            int f = tid * 4;
            int i = f >> 7, dout = f & 127;
            *(float4*)(s_x2 + f) = *(const float4*)(g_Wo_t + (c0 + i) * Dd + dout);
        }
        __syncthreads();
        if (tid >= 256)
            gemm_step(acc, s_stage, s_x2, gt0, gd0, c0);
        __syncthreads();
    }
    if (tid >= 256)
        gemm_write(acc, bo, out + base, Dd, gt0, gd0);
}

extern "C" void kernel_launch(void* const* d_in, const int* in_sizes, int n_in,
                              void* d_out, int out_size) {
    (void)in_sizes; (void)n_in; (void)out_size;
    const float* query = (const float*)d_in[0];
    const float* key   = (const float*)d_in[1];
    const float* value = (const float*)d_in[2];
    const int*   mask  = (const int*)d_in[3];
    const float* Wq = (const float*)d_in[4];
    const float* bq = (const float*)d_in[5];
    const float* Wk = (const float*)d_in[6];
    const float* bk = (const float*)d_in[7];
    const float* Wv = (const float*)d_in[8];
    const float* bv = (const float*)d_in[9];
    const float* Wo = (const float*)d_in[10];
    const float* bo = (const float*)d_in[11];
    float* out = (float*)d_out;

    cudaFuncSetAttribute(attn_kernel, cudaFuncAttributeMaxDynamicSharedMemorySize, SMEM_BYTES);

    prep_kernel<<<256, 256>>>(Wq, Wk, Wv, Wo);
    attn_kernel<<<Bb * Nn, 512, SMEM_BYTES>>>(query, key, value, mask,
                                              bq, bk, bv, bo, out);
}